// round 4
// baseline (speedup 1.0000x reference)
#include <cuda_runtime.h>

#define BB    64
#define LPROG 25
#define IMG   (128*196)     // 25088 floats per image state

typedef unsigned long long ull;

// ---------------- device scratch (no allocs allowed) ----------------
__device__ float g_V  [BB*IMG];
__device__ float g_OUT[BB*IMG];
__device__ float g_SAV[BB*IMG];
__device__ float g_X  [BB*IMG];
__device__ float g_H  [BB*IMG];     // also stem temp
__device__ float g_FLAT[BB*25088];  // 512*49 per image
__device__ float g_FC1[BB*1024];

// transposed weights: [bank][ic][k][oc]  (oc fastest)
__device__ float g_stem1t[1024*9*128];
__device__ float g_stem2t[128*9*128];
__device__ float g_uw1t[11*128*9*128];
__device__ float g_uw2t[11*128*9*128];
__device__ float g_bw1t[6*128*9*128];
__device__ float g_bw2t[6*128*9*128];
__device__ float g_bwpt[6*256*128];  // 1x1, [pi][ic(256)][oc(128)]
__device__ float g_clst[128*512];    // 1x1, [ic(128)][oc(512)]

// ---------------- f32x2 helpers ----------------
__device__ __forceinline__ ull pack2(float lo, float hi){
    ull r; asm("mov.b64 %0, {%1, %2};" : "=l"(r) : "f"(lo), "f"(hi)); return r;
}
__device__ __forceinline__ void fma2(ull &d, ull a, ull b){
    asm("fma.rn.f32x2 %0, %1, %2, %0;" : "+l"(d) : "l"(a), "l"(b));
}
__device__ __forceinline__ void unpack2(ull v, float &lo, float &hi){
    asm("mov.b64 {%0, %1}, %2;" : "=f"(lo), "=f"(hi) : "l"(v));
}

// ---------------- weight transpose:  src [nb][OC][IC][KK] -> dst [nb][IC][KK][OC] ----------------
__device__ __forceinline__ void tr_core(const float* __restrict__ src, float* __restrict__ dst,
                                        int nb, int OC, int IC, int KK){
    int total = nb*OC*IC*KK;
    for (int i = blockIdx.x*blockDim.x + threadIdx.x; i < total; i += gridDim.x*blockDim.x){
        int oc = i % OC;
        int r  = i / OC;
        int k  = r % KK; r /= KK;
        int ic = r % IC;
        int bank = r / IC;
        dst[i] = src[((bank*OC + oc)*IC + ic)*KK + k];
    }
}
// exactly 5 transpose launches so program_kernel is launch #6 (ncu -s 5 -c 1)
__global__ void trA(const float* s){ tr_core(s, g_stem1t, 1, 128, 1024, 9); }
__global__ void trB(const float* s){ tr_core(s, g_uw1t, 11, 128, 128, 9); }
__global__ void trC(const float* s){ tr_core(s, g_uw2t, 11, 128, 128, 9); }
__global__ void trD(const float* a, const float* b){
    tr_core(a, g_bw1t, 6, 128, 128, 9);
    tr_core(b, g_bw2t, 6, 128, 128, 9);
}
__global__ void trE(const float* s2, const float* bp, const float* cw){
    tr_core(s2, g_stem2t, 1, 128, 128, 9);
    tr_core(bp, g_bwpt,   6, 128, 256, 1);
    tr_core(cw, g_clst,   1, 512, 128, 1);
}

// ---------------- shared memory union for the persistent kernel ----------------
struct SmemConv { float2 in[8][16][16]; float w[8][9][32]; };   // 16384 + 9216 B
struct SmemProj { float2 in[16][196];   float w[16][32];   };   // 25088 + 2048 B
union  SmemU { SmemConv c; SmemProj p; };

// cluster-wide phase boundary: release writes + L1 invalidate (scope>=cluster), barrier
__device__ __forceinline__ void csync(){
    asm volatile("fence.acq_rel.cluster;" ::: "memory");
    asm volatile("barrier.cluster.arrive.aligned;" ::: "memory");
    asm volatile("barrier.cluster.wait.aligned;"   ::: "memory");
}

// ---------------- 3x3 conv slice: this CTA computes 32 output channels ----------------
// 256 threads = two 128-thread halves; half h covers oc [oc0+16h, oc0+16h+16).
// Within a half, thread tl<98 owns positions (tl, tl+98), 8 oc-pairs each.
// wt layout: [IC][9][128]. Staging is register-prefetched (sync; STS; sync; LDG next; compute).
__device__ void conv3x3_p(SmemU* sm, const float* __restrict__ src,
                          const float* __restrict__ wt, int oc0,
                          const float* __restrict__ bias,
                          const float* resid, float* dst,
                          float* dst2, float* dst3, int IC)
{
    const int t   = threadIdx.x;
    const int hid = t >> 7;
    const int tl  = t & 127;
    ull acc0[8], acc1[8];
#pragma unroll
    for (int j = 0; j < 8; j++){ acc0[j] = 0ull; acc1[j] = 0ull; }
    const int p0 = tl, p1 = tl + 98;
    const int y0 = p0/14, x0 = p0 - y0*14;
    const int y1 = p1/14, x1 = p1 - y1*14;
    const bool act = (tl < 98);

    float pin[8], pw[9];
    // prologue prefetch: chunk 0
#pragma unroll
    for (int e = 0; e < 8; e++){
        int i = t + e*256, ic = i >> 8, r = i & 255, yy = r >> 4, xx = r & 15;
        bool ok = (yy >= 1 && yy <= 14 && xx >= 1 && xx <= 14);
        pin[e] = ok ? src[ic*196 + (yy-1)*14 + (xx-1)] : 0.f;
    }
#pragma unroll
    for (int e = 0; e < 9; e++){
        int i = t + e*256, oc = i & 31, r = i >> 5, k = r % 9, ic = r / 9;
        pw[e] = wt[(ic*9 + k)*128 + oc0 + oc];
    }

    for (int ic0 = 0; ic0 < IC; ic0 += 8){
        __syncthreads();                       // previous chunk's compute done with smem
        {   // store prefetched chunk (linear addressing: in/w are contiguous)
            float2* inl = &sm->c.in[0][0][0];
            float*  wl  = &sm->c.w[0][0][0];
#pragma unroll
            for (int e = 0; e < 8; e++) inl[t + e*256] = make_float2(pin[e], pin[e]);
#pragma unroll
            for (int e = 0; e < 9; e++) wl[t + e*256] = pw[e];
        }
        __syncthreads();
        // prefetch next chunk (LDG latency hidden under compute below)
        if (ic0 + 8 < IC){
            const float* srcn = src + (ic0 + 8)*196;
            const float* wtn  = wt  + (ic0 + 8)*9*128;
#pragma unroll
            for (int e = 0; e < 8; e++){
                int i = t + e*256, ic = i >> 8, r = i & 255, yy = r >> 4, xx = r & 15;
                bool ok = (yy >= 1 && yy <= 14 && xx >= 1 && xx <= 14);
                pin[e] = ok ? srcn[ic*196 + (yy-1)*14 + (xx-1)] : 0.f;
            }
#pragma unroll
            for (int e = 0; e < 9; e++){
                int i = t + e*256, oc = i & 31, r = i >> 5, k = r % 9, ic = r / 9;
                pw[e] = wtn[(ic*9 + k)*128 + oc0 + oc];
            }
        }
        if (act){
#pragma unroll 1
            for (int ic = 0; ic < 8; ic++){
                ull ap[9], bp[9];
#pragma unroll
                for (int ky = 0; ky < 3; ky++)
#pragma unroll
                    for (int kx = 0; kx < 3; kx++){
                        ap[ky*3+kx] = *reinterpret_cast<const ull*>(&sm->c.in[ic][y0+ky][x0+kx]);
                        bp[ky*3+kx] = *reinterpret_cast<const ull*>(&sm->c.in[ic][y1+ky][x1+kx]);
                    }
#pragma unroll
                for (int g = 0; g < 4; g++){
#pragma unroll
                    for (int k = 0; k < 9; k++){
                        ulonglong2 w2 = *reinterpret_cast<const ulonglong2*>(
                            &sm->c.w[ic][k][hid*16 + g*4]);
                        fma2(acc0[2*g  ], ap[k], w2.x);
                        fma2(acc0[2*g+1], ap[k], w2.y);
                        fma2(acc1[2*g  ], bp[k], w2.x);
                        fma2(acc1[2*g+1], bp[k], w2.y);
                    }
                }
            }
        }
    }
    if (act){
#pragma unroll
        for (int j = 0; j < 8; j++){
            int oc = oc0 + hid*16 + 2*j;
            float a0, a1, c0, c1;
            unpack2(acc0[j], a0, a1);
            unpack2(acc1[j], c0, c1);
            float bz0 = bias[oc], bz1 = bias[oc+1];
            a0 += bz0; a1 += bz1; c0 += bz0; c1 += bz1;
            if (resid){
                a0 += resid[oc*196+p0];     a1 += resid[(oc+1)*196+p0];
                c0 += resid[oc*196+p1];     c1 += resid[(oc+1)*196+p1];
            }
            a0 = fmaxf(a0,0.f); a1 = fmaxf(a1,0.f);
            c0 = fmaxf(c0,0.f); c1 = fmaxf(c1,0.f);
            dst[oc*196+p0] = a0;  dst[(oc+1)*196+p0] = a1;
            dst[oc*196+p1] = c0;  dst[(oc+1)*196+p1] = c1;
            if (dst2){
                dst2[oc*196+p0] = a0; dst2[(oc+1)*196+p0] = a1;
                dst2[oc*196+p1] = c0; dst2[(oc+1)*196+p1] = c1;
            }
            if (dst3){
                dst3[oc*196+p0] = a0; dst3[(oc+1)*196+p0] = a1;
                dst3[oc*196+p1] = c0; dst3[(oc+1)*196+p1] = c1;
            }
        }
    }
}

// ---------------- binary 1x1 projection slice: 32 oc from concat(OUT,SAV) ----------------
__device__ void proj_p(SmemU* sm, const float* __restrict__ A, const float* __restrict__ S,
                       const float* __restrict__ wt, int oc0,
                       const float* __restrict__ bias, float* dst)
{
    const int t = threadIdx.x;
    const bool act = (t < 196);
    ull acc[16];
#pragma unroll
    for (int j = 0; j < 16; j++) acc[j] = 0ull;

    for (int icg = 0; icg < 16; icg++){
        const float* s = (icg < 8 ? A : S) + (icg & 7)*16*196;
        __syncthreads();
        for (int i = t; i < 16*196; i += 256){
            float v = s[i];
            (&sm->p.in[0][0])[i] = make_float2(v, v);
        }
        for (int i = t; i < 512; i += 256){
            int oc = i & 31, ic = i >> 5;
            sm->p.w[ic][oc] = wt[(icg*16 + ic)*128 + oc0 + oc];
        }
        __syncthreads();
        if (act){
#pragma unroll 4
            for (int ic = 0; ic < 16; ic++){
                ull ap = *reinterpret_cast<const ull*>(&sm->p.in[ic][t]);
#pragma unroll
                for (int g = 0; g < 8; g++){
                    ulonglong2 w2 = *reinterpret_cast<const ulonglong2*>(&sm->p.w[ic][g*4]);
                    fma2(acc[2*g  ], ap, w2.x);
                    fma2(acc[2*g+1], ap, w2.y);
                }
            }
        }
    }
    if (act){
#pragma unroll
        for (int j = 0; j < 16; j++){
            int oc = oc0 + 2*j;
            float a0, a1;
            unpack2(acc[j], a0, a1);
            a0 = fmaxf(a0 + bias[oc],   0.f);
            a1 = fmaxf(a1 + bias[oc+1], 0.f);
            dst[oc*196+t]     = a0;
            dst[(oc+1)*196+t] = a1;
        }
    }
}

// ---------------- persistent program kernel: 64 images x 4-CTA clusters ----------------
__global__ void __cluster_dims__(4,1,1) __launch_bounds__(256, 2)
program_kernel(const float* __restrict__ feats, const int* __restrict__ programs,
               const float* __restrict__ stem_b1, const float* __restrict__ stem_b2,
               const float* __restrict__ ub1, const float* __restrict__ ub2,
               const float* __restrict__ bbp, const float* __restrict__ bb1,
               const float* __restrict__ bb2)
{
    __shared__ SmemU sm;
    const int cta = blockIdx.x;
    const int b   = cta >> 2;
    const int oc0 = (cta & 3) * 32;
    float* OUT = g_OUT + b*IMG;
    float* SAV = g_SAV + b*IMG;
    float* X   = g_X   + b*IMG;
    float* H   = g_H   + b*IMG;
    float* V   = g_V   + b*IMG;

    // stem: conv3x3(1024->128) -> relu -> conv3x3(128->128) -> relu; init OUT=SAV=V
    conv3x3_p(&sm, feats + b*1024*196, g_stem1t, oc0, stem_b1, nullptr,
              H, nullptr, nullptr, 1024);
    csync();
    conv3x3_p(&sm, H, g_stem2t, oc0, stem_b2, nullptr, V, OUT, SAV, 128);
    csync();

    // program walk (reverse token order, matching reference scan of prog[::-1])
    for (int tpos = LPROG-1; tpos >= 0; tpos--){
        int tok = programs[b*LPROG + tpos];
        if (tok < 4) continue;                   // no-op tokens: no phases, no barriers
        if (tok >= 15){                          // binary module
            int pi = tok - 15;
            proj_p(&sm, OUT, SAV, g_bwpt + pi*256*128, oc0, bbp + pi*128, X);
            csync();
            conv3x3_p(&sm, X, g_bw1t + pi*(128*9*128), oc0, bb1 + pi*128, nullptr,
                      H, nullptr, nullptr, 128);
            csync();
            conv3x3_p(&sm, H, g_bw2t + pi*(128*9*128), oc0, bb2 + pi*128, X,
                      OUT, nullptr, nullptr, 128);
            csync();
        } else {                                 // scene (4) or unary (5..14)
            int pi = (tok == 4) ? 0 : tok - 4;
            const float* src = (tok == 4) ? V : OUT;
            if (tok == 4){
                // saved = old out (own slice; published at the next csync)
                for (int i = threadIdx.x; i < 32*196; i += 256){
                    int idx = oc0*196 + i;
                    SAV[idx] = OUT[idx];
                }
            }
            conv3x3_p(&sm, src, g_uw1t + pi*(128*9*128), oc0, ub1 + pi*128, nullptr,
                      H, nullptr, nullptr, 128);
            csync();
            conv3x3_p(&sm, H, g_uw2t + pi*(128*9*128), oc0, ub2 + pi*128, src,
                      OUT, nullptr, nullptr, 128);
            csync();
        }
    }
}

// ---------------- classifier: 1x1 conv 128->512 + relu + maxpool2 -> FLAT ----------------
__global__ void cls_kernel(const float* __restrict__ cls_b){
    int b = blockIdx.y;
    const int oc0 = blockIdx.x*32;
    __shared__ float s_in[16][196];
    __shared__ __align__(16) float s_w[16][32];
    __shared__ float s_c[32][196];
    const int t = threadIdx.x;
    ull acc0[16], acc1[16];
#pragma unroll
    for (int j = 0; j < 16; j++){ acc0[j] = 0ull; acc1[j] = 0ull; }
    const int p0 = t, p1 = t + 98;
    const bool active = (t < 98);
    const float* srcb = g_OUT + b*IMG;

    for (int icg = 0; icg < 8; icg++){
        for (int i = t; i < 16*196; i += 128){
            int ic = i/196, p = i - ic*196;
            s_in[ic][p] = srcb[(icg*16 + ic)*196 + p];
        }
        for (int i = t; i < 512; i += 128){
            int oc = i & 31, ic = i >> 5;
            s_w[ic][oc] = g_clst[(icg*16 + ic)*512 + oc0 + oc];
        }
        __syncthreads();
        if (active){
#pragma unroll 4
            for (int ic = 0; ic < 16; ic++){
                float av = s_in[ic][p0], bv = s_in[ic][p1];
                ull ap = pack2(av, av), bp = pack2(bv, bv);
#pragma unroll
                for (int g = 0; g < 8; g++){
                    ulonglong2 w2 = *reinterpret_cast<const ulonglong2*>(&s_w[ic][g*4]);
                    fma2(acc0[2*g  ], ap, w2.x);
                    fma2(acc0[2*g+1], ap, w2.y);
                    fma2(acc1[2*g  ], bp, w2.x);
                    fma2(acc1[2*g+1], bp, w2.y);
                }
            }
        }
        __syncthreads();
    }
    if (active){
#pragma unroll
        for (int j = 0; j < 16; j++){
            int oc = oc0 + 2*j;
            float a0, a1, c0, c1;
            unpack2(acc0[j], a0, a1);
            unpack2(acc1[j], c0, c1);
            float bz0 = cls_b[oc], bz1 = cls_b[oc+1];
            s_c[2*j  ][p0] = fmaxf(a0+bz0, 0.f);
            s_c[2*j+1][p0] = fmaxf(a1+bz1, 0.f);
            s_c[2*j  ][p1] = fmaxf(c0+bz0, 0.f);
            s_c[2*j+1][p1] = fmaxf(c1+bz1, 0.f);
        }
    }
    __syncthreads();
    // 2x2 maxpool -> flat [ch*49 + py*7 + px]
    for (int i = t; i < 32*49; i += 128){
        int ocl = i/49, cell = i - ocl*49;
        int py = cell/7, px = cell - py*7;
        int base = 28*py + 2*px;
        float m = fmaxf(fmaxf(s_c[ocl][base], s_c[ocl][base+1]),
                        fmaxf(s_c[ocl][base+14], s_c[ocl][base+15]));
        g_FLAT[b*25088 + (oc0 + ocl)*49 + cell] = m;
    }
}

// ---------------- fc1: [64,25088] x [1024,25088]^T, k-split with atomics ----------------
__global__ void zero_fc1(){
    int i = blockIdx.x*blockDim.x + threadIdx.x;
    if (i < BB*1024) g_FC1[i] = 0.f;
}
__global__ void fc1_kernel(const float* __restrict__ w){
    int n0 = blockIdx.x*64;
    int k0 = blockIdx.y*1568;
    __shared__ float sA[64][33];
    __shared__ float sB[64][33];
    const int t = threadIdx.x;
    const int tx = t & 15, ty = t >> 4;
    float acc[4][4] = {};
    for (int kk = 0; kk < 1568; kk += 32){
        for (int i = t; i < 2048; i += 256){
            int row = i >> 5, k = i & 31;
            sA[row][k] = g_FLAT[row*25088 + k0 + kk + k];
            sB[row][k] = w[(n0+row)*25088 + k0 + kk + k];
        }
        __syncthreads();
#pragma unroll 8
        for (int k = 0; k < 32; k++){
            float a[4], bv[4];
#pragma unroll
            for (int i = 0; i < 4; i++) a[i] = sA[ty*4+i][k];
#pragma unroll
            for (int j = 0; j < 4; j++) bv[j] = sB[tx*4+j][k];
#pragma unroll
            for (int i = 0; i < 4; i++)
#pragma unroll
                for (int j = 0; j < 4; j++) acc[i][j] += a[i]*bv[j];
        }
        __syncthreads();
    }
#pragma unroll
    for (int i = 0; i < 4; i++)
#pragma unroll
        for (int j = 0; j < 4; j++)
            atomicAdd(&g_FC1[(ty*4+i)*1024 + n0 + tx*4 + j], acc[i][j]);
}

// ---------------- fc2: out = relu(fc1+b1) @ fc2_w^T + b2 ----------------
__global__ void fc2_kernel(const float* __restrict__ fc1_b, const float* __restrict__ w2,
                           const float* __restrict__ b2, float* __restrict__ out){
    int b = blockIdx.x;
    const int t = threadIdx.x;
    int n2 = t >> 3, kl = t & 7;
    float acc = 0.f;
    for (int k = kl; k < 1024; k += 8)
        acc += fmaxf(g_FC1[b*1024 + k] + fc1_b[k], 0.f) * w2[n2*1024 + k];
    __shared__ float red[256];
    red[t] = acc;
    __syncthreads();
    if (kl == 0){
        float s = red[t];
#pragma unroll
        for (int q = 1; q < 8; q++) s += red[t+q];
        out[b*32 + n2] = s + b2[n2];
    }
}

// ---------------- launch ----------------
extern "C" void kernel_launch(void* const* d_in, const int* in_sizes, int n_in,
                              void* d_out, int out_size){
    const float* feats    = (const float*)d_in[0];
    const int*   programs = (const int*)  d_in[1];
    const float* stem_w1  = (const float*)d_in[2];
    const float* stem_b1  = (const float*)d_in[3];
    const float* stem_w2  = (const float*)d_in[4];
    const float* stem_b2  = (const float*)d_in[5];
    const float* uw1      = (const float*)d_in[6];
    const float* ub1      = (const float*)d_in[7];
    const float* uw2      = (const float*)d_in[8];
    const float* ub2      = (const float*)d_in[9];
    const float* bwp      = (const float*)d_in[10];
    const float* bbp      = (const float*)d_in[11];
    const float* bw1      = (const float*)d_in[12];
    const float* bb1      = (const float*)d_in[13];
    const float* bw2      = (const float*)d_in[14];
    const float* bb2      = (const float*)d_in[15];
    const float* cls_w    = (const float*)d_in[16];
    const float* cls_b    = (const float*)d_in[17];
    const float* fc1_w    = (const float*)d_in[18];
    const float* fc1_b    = (const float*)d_in[19];
    const float* fc2_w    = (const float*)d_in[20];
    const float* fc2_b    = (const float*)d_in[21];
    float* out = (float*)d_out;

    // 5 transpose launches (deterministic every call), then program = launch #6
    trA<<<512, 256>>>(stem_w1);
    trB<<<512, 256>>>(uw1);
    trC<<<512, 256>>>(uw2);
    trD<<<512, 256>>>(bw1, bw2);
    trE<<<512, 256>>>(stem_w2, bwp, cls_w);

    program_kernel<<<BB*4, 256>>>(feats, programs, stem_b1, stem_b2,
                                  ub1, ub2, bbp, bb1, bb2);

    cls_kernel<<<dim3(16, BB), 128>>>(cls_b);
    zero_fc1<<<256, 256>>>();
    fc1_kernel<<<dim3(16, 16), 256>>>(fc1_w);
    fc2_kernel<<<BB, 256>>>(fc1_b, fc2_w, fc2_b, out);
}

// round 5
// speedup vs baseline: 2.6730x; 2.6730x over previous
#include <cuda_runtime.h>

#define BB    64
#define LPROG 25
#define IMG   (128*196)     // 25088 floats per image state

typedef unsigned long long ull;

// ---------------- device scratch (no allocs allowed) ----------------
__device__ float g_V  [BB*IMG];
__device__ float g_OUT[BB*IMG];
__device__ float g_SAV[BB*IMG];
__device__ float g_X  [BB*IMG];
__device__ float g_H  [BB*IMG];     // also stem temp
__device__ float g_FLAT[BB*25088];  // 512*49 per image
__device__ float g_FC1[BB*1024];

// transposed weights: [bank][ic][k][oc]  (oc fastest)
__device__ float g_stem1t[1024*9*128];
__device__ float g_stem2t[128*9*128];
__device__ float g_uw1t[11*128*9*128];
__device__ float g_uw2t[11*128*9*128];
__device__ float g_bw1t[6*128*9*128];
__device__ float g_bw2t[6*128*9*128];
__device__ float g_bwpt[6*256*128];  // 1x1, [pi][ic(256)][oc(128)]
__device__ float g_clst[128*512];    // 1x1, [ic(128)][oc(512)]

// ---------------- f32x2 helpers (epilogue kernels) ----------------
__device__ __forceinline__ ull pack2(float lo, float hi){
    ull r; asm("mov.b64 %0, {%1, %2};" : "=l"(r) : "f"(lo), "f"(hi)); return r;
}
__device__ __forceinline__ void fma2(ull &d, ull a, ull b){
    asm("fma.rn.f32x2 %0, %1, %2, %0;" : "+l"(d) : "l"(a), "l"(b));
}
__device__ __forceinline__ void unpack2(ull v, float &lo, float &hi){
    asm("mov.b64 {%0, %1}, %2;" : "=f"(lo), "=f"(hi) : "l"(v));
}

// ---------------- bf16 split helpers ----------------
// pack {lo half = v0, hi half = v1} as bf16x2 (rn)
__device__ __forceinline__ unsigned packbf(float v0, float v1){
    unsigned r; asm("cvt.rn.bf16x2.f32 %0, %1, %2;" : "=r"(r) : "f"(v1), "f"(v0));
    return r;
}
// v = hi + lo split, packed pairs (error-compensated bf16)
__device__ __forceinline__ void split2(float v0, float v1, unsigned &hi, unsigned &lo){
    hi = packbf(v0, v1);
    float h0 = __uint_as_float(hi << 16);
    float h1 = __uint_as_float(hi & 0xFFFF0000u);
    lo = packbf(v0 - h0, v1 - h1);
}
// D += A(16x16) * B(16x8), bf16 in, f32 accum
__device__ __forceinline__ void mma16816(float c[4], const unsigned a[4],
                                         unsigned b0, unsigned b1){
    asm volatile("mma.sync.aligned.m16n8k16.row.col.f32.bf16.bf16.f32 "
        "{%0,%1,%2,%3}, {%4,%5,%6,%7}, {%8,%9}, {%0,%1,%2,%3};"
        : "+f"(c[0]), "+f"(c[1]), "+f"(c[2]), "+f"(c[3])
        : "r"(a[0]), "r"(a[1]), "r"(a[2]), "r"(a[3]), "r"(b0), "r"(b1));
}

// ---------------- weight transpose:  src [nb][OC][IC][KK] -> dst [nb][IC][KK][OC] ----------------
__device__ __forceinline__ void tr_core(const float* __restrict__ src, float* __restrict__ dst,
                                        int nb, int OC, int IC, int KK){
    int total = nb*OC*IC*KK;
    for (int i = blockIdx.x*blockDim.x + threadIdx.x; i < total; i += gridDim.x*blockDim.x){
        int oc = i % OC;
        int r  = i / OC;
        int k  = r % KK; r /= KK;
        int ic = r % IC;
        int bank = r / IC;
        dst[i] = src[((bank*OC + oc)*IC + ic)*KK + k];
    }
}
__global__ void trA(const float* s){ tr_core(s, g_stem1t, 1, 128, 1024, 9); }
__global__ void trB(const float* s){ tr_core(s, g_uw1t, 11, 128, 128, 9); }
__global__ void trC(const float* s){ tr_core(s, g_uw2t, 11, 128, 128, 9); }
__global__ void trD(const float* a, const float* b){
    tr_core(a, g_bw1t, 6, 128, 128, 9);
    tr_core(b, g_bw2t, 6, 128, 128, 9);
}
__global__ void trE(const float* s2, const float* bp, const float* cw){
    tr_core(s2, g_stem2t, 1, 128, 128, 9);
    tr_core(bp, g_bwpt,   6, 128, 256, 1);
    tr_core(cw, g_clst,   1, 512, 128, 1);
}

// ---------------- shared memory (bf16x2 packed hi/lo, conflict-free strides) ----------------
// conv: in plane stride 264 words (8 mod 32), w: tap stride 40, ic stride 360 (8 mod 32)
struct SmemConvM { unsigned inH[8*264], inL[8*264], wH[8*360], wL[8*360]; };
struct SmemProjM { unsigned inH[8*232], inL[8*232], wH[8*40],  wL[8*40];  };
union __align__(16) SmemU { SmemConvM c; SmemProjM p; };

// cluster-wide phase boundary (known-good config from R3)
__device__ __forceinline__ void csync(){
    __threadfence();
    asm volatile("barrier.cluster.arrive.aligned;" ::: "memory");
    asm volatile("barrier.cluster.wait.aligned;"   ::: "memory");
}

// ---------------- 3x3 conv slice via bf16-split tensor cores ----------------
// CTA = 32 oc; 8 warps: mh=wid>>2 picks 16-oc half, nw=wid&3 picks 56-position strip.
// Conv = 9 shifted GEMMs (taps), K processed in 16-ic chunks (one m16n8k16 K-step).
__device__ void conv3x3_mma(SmemU* sm, const float* __restrict__ src,
                            const float* __restrict__ wt, int oc0,
                            const float* __restrict__ bias,
                            const float* resid, float* dst,
                            float* dst2, float* dst3, int IC)
{
    const int t = threadIdx.x;
    const int lane = t & 31, wid = t >> 5;
    const int mh = wid >> 2, nw = wid & 3;
    const int gr = lane >> 2, ct = lane & 3;
    float acc[7][4] = {};
    int cb[7];
#pragma unroll
    for (int tt = 0; tt < 7; tt++){
        int p = nw*56 + tt*8 + gr;
        if (p < 196){ int y = p/14, x = p - y*14; cb[tt] = y*16 + x; }
        else cb[tt] = -1;                 // clamp to halo zero cell (word 15)
    }

    for (int ic0 = 0; ic0 < IC; ic0 += 16){
        __syncthreads();
        // stage inputs: 8 ic-pairs x 256 padded cells (16x16, halo zero)
#pragma unroll
        for (int e = 0; e < 8; e++){
            int i = t + e*256;
            int icp = i >> 8, cell = i & 255, yy = cell >> 4, xx = cell & 15;
            float v0 = 0.f, v1 = 0.f;
            if (yy >= 1 && yy <= 14 && xx >= 1 && xx <= 14){
                const float* s = src + (ic0 + 2*icp)*196 + (yy-1)*14 + (xx-1);
                v0 = s[0]; v1 = s[196];
            }
            unsigned h, l; split2(v0, v1, h, l);
            sm->c.inH[icp*264 + cell] = h;
            sm->c.inL[icp*264 + cell] = l;
        }
        // stage weights: 8 ic-pairs x 9 taps x 32 oc
#pragma unroll
        for (int e = 0; e < 9; e++){
            int i = t + e*256;
            int oc = i & 31, r = i >> 5, tap = r % 9, icp = r / 9;
            const float* wp = wt + ((ic0 + 2*icp)*9 + tap)*128 + oc0 + oc;
            unsigned h, l; split2(wp[0], wp[9*128], h, l);
            sm->c.wH[icp*360 + tap*40 + oc] = h;
            sm->c.wL[icp*360 + tap*40 + oc] = l;
        }
        __syncthreads();
#pragma unroll 1
        for (int tap = 0; tap < 9; tap++){
            const int toff = (tap/3)*16 + (tap - (tap/3)*3);
            unsigned aH[4], aL[4];
            const int wb = tap*40 + 16*mh + gr;
            aH[0] = sm->c.wH[ct*360 + wb];      aH[1] = sm->c.wH[ct*360 + wb + 8];
            aH[2] = sm->c.wH[(ct+4)*360 + wb];  aH[3] = sm->c.wH[(ct+4)*360 + wb + 8];
            aL[0] = sm->c.wL[ct*360 + wb];      aL[1] = sm->c.wL[ct*360 + wb + 8];
            aL[2] = sm->c.wL[(ct+4)*360 + wb];  aL[3] = sm->c.wL[(ct+4)*360 + wb + 8];
#pragma unroll
            for (int tt = 0; tt < 7; tt++){
                int w = (cb[tt] >= 0) ? cb[tt] + toff : 15;
                unsigned bH0 = sm->c.inH[ct*264 + w];
                unsigned bH1 = sm->c.inH[(ct+4)*264 + w];
                unsigned bL0 = sm->c.inL[ct*264 + w];
                unsigned bL1 = sm->c.inL[(ct+4)*264 + w];
                mma16816(acc[tt], aH, bH0, bH1);
                mma16816(acc[tt], aH, bL0, bL1);
                mma16816(acc[tt], aL, bH0, bH1);
            }
        }
    }
    // epilogue: bias (+residual) + relu, store
    const int ocA = oc0 + 16*mh + gr, ocB = ocA + 8;
    const float bA = bias[ocA], bB = bias[ocB];
#pragma unroll
    for (int tt = 0; tt < 7; tt++){
        int p0 = nw*56 + tt*8 + 2*ct, p1 = p0 + 1;
        float v00 = acc[tt][0] + bA, v01 = acc[tt][1] + bA;
        float v10 = acc[tt][2] + bB, v11 = acc[tt][3] + bB;
        if (resid){
            if (p0 < 196){ v00 += resid[ocA*196+p0]; v10 += resid[ocB*196+p0]; }
            if (p1 < 196){ v01 += resid[ocA*196+p1]; v11 += resid[ocB*196+p1]; }
        }
        v00 = fmaxf(v00,0.f); v01 = fmaxf(v01,0.f);
        v10 = fmaxf(v10,0.f); v11 = fmaxf(v11,0.f);
        if (p0 < 196){
            dst[ocA*196+p0] = v00; dst[ocB*196+p0] = v10;
            if (dst2){ dst2[ocA*196+p0]=v00; dst2[ocB*196+p0]=v10; }
            if (dst3){ dst3[ocA*196+p0]=v00; dst3[ocB*196+p0]=v10; }
        }
        if (p1 < 196){
            dst[ocA*196+p1] = v01; dst[ocB*196+p1] = v11;
            if (dst2){ dst2[ocA*196+p1]=v01; dst2[ocB*196+p1]=v11; }
            if (dst3){ dst3[ocA*196+p1]=v01; dst3[ocB*196+p1]=v11; }
        }
    }
}

// ---------------- binary 1x1 projection via bf16-split tensor cores ----------------
__device__ void proj_mma(SmemU* sm, const float* __restrict__ A, const float* __restrict__ S,
                         const float* __restrict__ wt, int oc0,
                         const float* __restrict__ bias, float* dst)
{
    const int t = threadIdx.x;
    const int lane = t & 31, wid = t >> 5;
    const int mh = wid >> 2, nw = wid & 3;
    const int gr = lane >> 2, ct = lane & 3;
    float acc[7][4] = {};

    for (int ic0 = 0; ic0 < 256; ic0 += 16){
        __syncthreads();
        // stage inputs: 8 ic-pairs x 224 positions (196 real + zero pad)
        for (int i = t; i < 8*224; i += 256){
            int icp = i / 224, pos = i - icp*224;
            int ic = ic0 + 2*icp;
            float v0 = 0.f, v1 = 0.f;
            if (pos < 196){
                v0 = (ic   < 128 ? A[ic*196 + pos]        : S[(ic-128)*196 + pos]);
                v1 = (ic+1 < 128 ? A[(ic+1)*196 + pos]    : S[(ic+1-128)*196 + pos]);
            }
            unsigned h, l; split2(v0, v1, h, l);
            sm->p.inH[icp*232 + pos] = h;
            sm->p.inL[icp*232 + pos] = l;
        }
        {   // stage weights: 8 ic-pairs x 32 oc (exactly 256 words)
            int oc = t & 31, icp = t >> 5;
            int ic = ic0 + 2*icp;
            unsigned h, l; split2(wt[ic*128 + oc0 + oc], wt[(ic+1)*128 + oc0 + oc], h, l);
            sm->p.wH[icp*40 + oc] = h;
            sm->p.wL[icp*40 + oc] = l;
        }
        __syncthreads();
        unsigned aH[4], aL[4];
        aH[0] = sm->p.wH[ct*40 + 16*mh + gr];      aH[1] = sm->p.wH[ct*40 + 16*mh + gr + 8];
        aH[2] = sm->p.wH[(ct+4)*40 + 16*mh + gr];  aH[3] = sm->p.wH[(ct+4)*40 + 16*mh + gr + 8];
        aL[0] = sm->p.wL[ct*40 + 16*mh + gr];      aL[1] = sm->p.wL[ct*40 + 16*mh + gr + 8];
        aL[2] = sm->p.wL[(ct+4)*40 + 16*mh + gr];  aL[3] = sm->p.wL[(ct+4)*40 + 16*mh + gr + 8];
#pragma unroll
        for (int tt = 0; tt < 7; tt++){
            int w = nw*56 + tt*8 + gr;
            unsigned bH0 = sm->p.inH[ct*232 + w];
            unsigned bH1 = sm->p.inH[(ct+4)*232 + w];
            unsigned bL0 = sm->p.inL[ct*232 + w];
            unsigned bL1 = sm->p.inL[(ct+4)*232 + w];
            mma16816(acc[tt], aH, bH0, bH1);
            mma16816(acc[tt], aH, bL0, bL1);
            mma16816(acc[tt], aL, bH0, bH1);
        }
    }
    const int ocA = oc0 + 16*mh + gr, ocB = ocA + 8;
    const float bA = bias[ocA], bB = bias[ocB];
#pragma unroll
    for (int tt = 0; tt < 7; tt++){
        int p0 = nw*56 + tt*8 + 2*ct, p1 = p0 + 1;
        if (p0 < 196){
            dst[ocA*196+p0] = fmaxf(acc[tt][0] + bA, 0.f);
            dst[ocB*196+p0] = fmaxf(acc[tt][2] + bB, 0.f);
        }
        if (p1 < 196){
            dst[ocA*196+p1] = fmaxf(acc[tt][1] + bA, 0.f);
            dst[ocB*196+p1] = fmaxf(acc[tt][3] + bB, 0.f);
        }
    }
}

// ---------------- persistent program kernel: 64 images x 4-CTA clusters ----------------
__global__ void __cluster_dims__(4,1,1) __launch_bounds__(256, 2)
program_kernel(const float* __restrict__ feats, const int* __restrict__ programs,
               const float* __restrict__ stem_b1, const float* __restrict__ stem_b2,
               const float* __restrict__ ub1, const float* __restrict__ ub2,
               const float* __restrict__ bbp, const float* __restrict__ bb1,
               const float* __restrict__ bb2)
{
    __shared__ SmemU sm;
    const int cta = blockIdx.x;
    const int b   = cta >> 2;
    const int oc0 = (cta & 3) * 32;
    float* OUT = g_OUT + b*IMG;
    float* SAV = g_SAV + b*IMG;
    float* X   = g_X   + b*IMG;
    float* H   = g_H   + b*IMG;
    float* V   = g_V   + b*IMG;

    // stem: conv3x3(1024->128) -> relu -> conv3x3(128->128) -> relu; init OUT=SAV=V
    conv3x3_mma(&sm, feats + b*1024*196, g_stem1t, oc0, stem_b1, nullptr,
                H, nullptr, nullptr, 1024);
    csync();
    conv3x3_mma(&sm, H, g_stem2t, oc0, stem_b2, nullptr, V, OUT, SAV, 128);
    csync();

    // program walk (reverse token order, matching reference scan of prog[::-1])
    for (int tpos = LPROG-1; tpos >= 0; tpos--){
        int tok = programs[b*LPROG + tpos];
        if (tok < 4) continue;                   // no-op tokens: no phases, no barriers
        if (tok >= 15){                          // binary module
            int pi = tok - 15;
            proj_mma(&sm, OUT, SAV, g_bwpt + pi*256*128, oc0, bbp + pi*128, X);
            csync();
            conv3x3_mma(&sm, X, g_bw1t + pi*(128*9*128), oc0, bb1 + pi*128, nullptr,
                        H, nullptr, nullptr, 128);
            csync();
            conv3x3_mma(&sm, H, g_bw2t + pi*(128*9*128), oc0, bb2 + pi*128, X,
                        OUT, nullptr, nullptr, 128);
            csync();
        } else {                                 // scene (4) or unary (5..14)
            int pi = (tok == 4) ? 0 : tok - 4;
            const float* src = (tok == 4) ? V : OUT;
            if (tok == 4){
                // saved = old out (own slice; published at the next csync)
                for (int i = threadIdx.x; i < 32*196; i += 256){
                    int idx = oc0*196 + i;
                    SAV[idx] = OUT[idx];
                }
            }
            conv3x3_mma(&sm, src, g_uw1t + pi*(128*9*128), oc0, ub1 + pi*128, nullptr,
                        H, nullptr, nullptr, 128);
            csync();
            conv3x3_mma(&sm, H, g_uw2t + pi*(128*9*128), oc0, ub2 + pi*128, src,
                        OUT, nullptr, nullptr, 128);
            csync();
        }
    }
}

// ---------------- classifier: 1x1 conv 128->512 + relu + maxpool2 -> FLAT ----------------
__global__ void cls_kernel(const float* __restrict__ cls_b){
    int b = blockIdx.y;
    const int oc0 = blockIdx.x*32;
    __shared__ float s_in[16][196];
    __shared__ __align__(16) float s_w[16][32];
    __shared__ float s_c[32][196];
    const int t = threadIdx.x;
    ull acc0[16], acc1[16];
#pragma unroll
    for (int j = 0; j < 16; j++){ acc0[j] = 0ull; acc1[j] = 0ull; }
    const int p0 = t, p1 = t + 98;
    const bool active = (t < 98);
    const float* srcb = g_OUT + b*IMG;

    for (int icg = 0; icg < 8; icg++){
        for (int i = t; i < 16*196; i += 128){
            int ic = i/196, p = i - ic*196;
            s_in[ic][p] = srcb[(icg*16 + ic)*196 + p];
        }
        for (int i = t; i < 512; i += 128){
            int oc = i & 31, ic = i >> 5;
            s_w[ic][oc] = g_clst[(icg*16 + ic)*512 + oc0 + oc];
        }
        __syncthreads();
        if (active){
#pragma unroll 4
            for (int ic = 0; ic < 16; ic++){
                float av = s_in[ic][p0], bv = s_in[ic][p1];
                ull ap = pack2(av, av), bp = pack2(bv, bv);
#pragma unroll
                for (int g = 0; g < 8; g++){
                    ulonglong2 w2 = *reinterpret_cast<const ulonglong2*>(&s_w[ic][g*4]);
                    fma2(acc0[2*g  ], ap, w2.x);
                    fma2(acc0[2*g+1], ap, w2.y);
                    fma2(acc1[2*g  ], bp, w2.x);
                    fma2(acc1[2*g+1], bp, w2.y);
                }
            }
        }
        __syncthreads();
    }
    if (active){
#pragma unroll
        for (int j = 0; j < 16; j++){
            int oc = oc0 + 2*j;
            float a0, a1, c0, c1;
            unpack2(acc0[j], a0, a1);
            unpack2(acc1[j], c0, c1);
            float bz0 = cls_b[oc], bz1 = cls_b[oc+1];
            s_c[2*j  ][p0] = fmaxf(a0+bz0, 0.f);
            s_c[2*j+1][p0] = fmaxf(a1+bz1, 0.f);
            s_c[2*j  ][p1] = fmaxf(c0+bz0, 0.f);
            s_c[2*j+1][p1] = fmaxf(c1+bz1, 0.f);
        }
    }
    __syncthreads();
    for (int i = t; i < 32*49; i += 128){
        int ocl = i/49, cell = i - ocl*49;
        int py = cell/7, px = cell - py*7;
        int base = 28*py + 2*px;
        float m = fmaxf(fmaxf(s_c[ocl][base], s_c[ocl][base+1]),
                        fmaxf(s_c[ocl][base+14], s_c[ocl][base+15]));
        g_FLAT[b*25088 + (oc0 + ocl)*49 + cell] = m;
    }
}

// ---------------- fc1: [64,25088] x [1024,25088]^T, k-split with atomics ----------------
__global__ void zero_fc1(){
    int i = blockIdx.x*blockDim.x + threadIdx.x;
    if (i < BB*1024) g_FC1[i] = 0.f;
}
__global__ void fc1_kernel(const float* __restrict__ w){
    int n0 = blockIdx.x*64;
    int k0 = blockIdx.y*1568;
    __shared__ float sA[64][33];
    __shared__ float sB[64][33];
    const int t = threadIdx.x;
    const int tx = t & 15, ty = t >> 4;
    float acc[4][4] = {};
    for (int kk = 0; kk < 1568; kk += 32){
        for (int i = t; i < 2048; i += 256){
            int row = i >> 5, k = i & 31;
            sA[row][k] = g_FLAT[row*25088 + k0 + kk + k];
            sB[row][k] = w[(n0+row)*25088 + k0 + kk + k];
        }
        __syncthreads();
#pragma unroll 8
        for (int k = 0; k < 32; k++){
            float a[4], bv[4];
#pragma unroll
            for (int i = 0; i < 4; i++) a[i] = sA[ty*4+i][k];
#pragma unroll
            for (int j = 0; j < 4; j++) bv[j] = sB[tx*4+j][k];
#pragma unroll
            for (int i = 0; i < 4; i++)
#pragma unroll
                for (int j = 0; j < 4; j++) acc[i][j] += a[i]*bv[j];
        }
        __syncthreads();
    }
#pragma unroll
    for (int i = 0; i < 4; i++)
#pragma unroll
        for (int j = 0; j < 4; j++)
            atomicAdd(&g_FC1[(ty*4+i)*1024 + n0 + tx*4 + j], acc[i][j]);
}

// ---------------- fc2: out = relu(fc1+b1) @ fc2_w^T + b2 ----------------
__global__ void fc2_kernel(const float* __restrict__ fc1_b, const float* __restrict__ w2,
                           const float* __restrict__ b2, float* __restrict__ out){
    int b = blockIdx.x;
    const int t = threadIdx.x;
    int n2 = t >> 3, kl = t & 7;
    float acc = 0.f;
    for (int k = kl; k < 1024; k += 8)
        acc += fmaxf(g_FC1[b*1024 + k] + fc1_b[k], 0.f) * w2[n2*1024 + k];
    __shared__ float red[256];
    red[t] = acc;
    __syncthreads();
    if (kl == 0){
        float s = red[t];
#pragma unroll
        for (int q = 1; q < 8; q++) s += red[t+q];
        out[b*32 + n2] = s + b2[n2];
    }
}

// ---------------- launch ----------------
extern "C" void kernel_launch(void* const* d_in, const int* in_sizes, int n_in,
                              void* d_out, int out_size){
    const float* feats    = (const float*)d_in[0];
    const int*   programs = (const int*)  d_in[1];
    const float* stem_w1  = (const float*)d_in[2];
    const float* stem_b1  = (const float*)d_in[3];
    const float* stem_w2  = (const float*)d_in[4];
    const float* stem_b2  = (const float*)d_in[5];
    const float* uw1      = (const float*)d_in[6];
    const float* ub1      = (const float*)d_in[7];
    const float* uw2      = (const float*)d_in[8];
    const float* ub2      = (const float*)d_in[9];
    const float* bwp      = (const float*)d_in[10];
    const float* bbp      = (const float*)d_in[11];
    const float* bw1      = (const float*)d_in[12];
    const float* bb1      = (const float*)d_in[13];
    const float* bw2      = (const float*)d_in[14];
    const float* bb2      = (const float*)d_in[15];
    const float* cls_w    = (const float*)d_in[16];
    const float* cls_b    = (const float*)d_in[17];
    const float* fc1_w    = (const float*)d_in[18];
    const float* fc1_b    = (const float*)d_in[19];
    const float* fc2_w    = (const float*)d_in[20];
    const float* fc2_b    = (const float*)d_in[21];
    float* out = (float*)d_out;

    trA<<<512, 256>>>(stem_w1);
    trB<<<512, 256>>>(uw1);
    trC<<<512, 256>>>(uw2);
    trD<<<512, 256>>>(bw1, bw2);
    trE<<<512, 256>>>(stem_w2, bwp, cls_w);

    program_kernel<<<BB*4, 256>>>(feats, programs, stem_b1, stem_b2,
                                  ub1, ub2, bbp, bb1, bb2);

    cls_kernel<<<dim3(16, BB), 128>>>(cls_b);
    zero_fc1<<<256, 256>>>();
    fc1_kernel<<<dim3(16, 16), 256>>>(fc1_w);
    fc2_kernel<<<BB, 256>>>(fc1_b, fc2_w, fc2_b, out);
}